// round 15
// baseline (speedup 1.0000x reference)
#include <cuda_runtime.h>
#include <cuda_fp16.h>
#include <mma.h>
#include <cstdint>

using namespace nvcuda;

// ---------------- problem constants ----------------
#define N_ATOMS 100000
#define M_NBR   12
#define F_ATOM  64
#define IN_DIM  169
#define OUT_DIM 128
#define NROWS   (N_ATOMS * M_NBR)        // 1,200,000
#define MTILES  (NROWS / 64)             // 18750 (64-row tiles)
#define PQTILES ((N_ATOMS + 127) / 128)  // 782
#define KP3     48
#define NSTRIPE 64
#define BN_EPS  1e-5f

// ---------------- device scratch ----------------
__device__ __align__(16) __half g_w12[64 * 256];      // [k][o]: o<128 -> W1, o>=128 -> W2
__device__ __align__(16) __half g_w3[KP3 * 128];      // [k][o], rows 41..47 zero
__device__ __align__(16) __half g_p[(size_t)N_ATOMS * 128];   // P + bias, fp16
__device__ __align__(16) __half g_q[(size_t)N_ATOMS * 128];   // Q, fp16
__device__ __half  g_gated[(size_t)NROWS * OUT_DIM];  // 307 MB
__device__ float   g_nbrsum[N_ATOMS * F_ATOM];
__device__ double  g_stats1[NSTRIPE][2 * OUT_DIM];
__device__ double  g_stats2[NSTRIPE][2 * F_ATOM];
__device__ float   g_bn1_scale[OUT_DIM], g_bn1_shift[OUT_DIM];
__device__ float   g_bn2_scale[F_ATOM],  g_bn2_shift[F_ATOM];

// ---------------- fast activations ----------------
__device__ __forceinline__ float softplus_f(float x) {
    return fmaxf(x, 0.f) + __logf(1.f + __expf(-fabsf(x)));
}
__device__ __forceinline__ float sigmoid_f(float x) {
    return __fdividef(1.f, 1.f + __expf(-x));
}

// ---------------- kernel 0: zero stats + build fp16 weight images ----------------
__global__ void prep_kernel(const float* __restrict__ fc_w) {
    int i = blockIdx.x * 256 + threadIdx.x;   // 64*256 = 16384
    if (i < NSTRIPE * 2 * OUT_DIM) ((double*)g_stats1)[i] = 0.0;
    if (i < NSTRIPE * 2 * F_ATOM)  ((double*)g_stats2)[i] = 0.0;
    if (i < 64 * 256) {
        int k = i >> 8, c = i & 255;
        float v = (c < 128) ? fc_w[c * IN_DIM + k] : fc_w[(c - 128) * IN_DIM + 64 + k];
        g_w12[i] = __float2half_rn(v);
    }
    if (i < KP3 * 128) {
        int k = i >> 7, o = i & 127;
        g_w3[i] = __float2half_rn(k < 41 ? fc_w[o * IN_DIM + 128 + k] : 0.f);
    }
}

// ---------------- kernel 1: P = atom@W1^T + b (fp16), Q = atom@W2^T (fp16) ----------------
#define PQ_ALD  72
#define PQ_BLD  264
#define PQ_SMA  0
#define PQ_SMB  18432
#define PQ_CS   0
#define PQ_BIAS 67584
#define PQ_SM   (67584 + 512)
#define CLD     132

__global__ void __launch_bounds__(512, 1) pq_kernel(const float* __restrict__ atom,
                                                    const float* __restrict__ bias) {
    extern __shared__ char smem[];
    __half* As = (__half*)(smem + PQ_SMA);
    __half* Bs = (__half*)(smem + PQ_SMB);
    float*  cs = (float*)(smem + PQ_CS);
    float*  bs = (float*)(smem + PQ_BIAS);

    const int tid = threadIdx.x;
    const int r0  = blockIdx.x * 128;

    if (tid < 128) bs[tid] = bias[tid];

    for (int i = tid; i < 64 * 32; i += 512) {
        int row = i >> 5, seg = i & 31;
        *(uint4*)(Bs + row * PQ_BLD + seg * 8) = *(const uint4*)(g_w12 + row * 256 + seg * 8);
    }
    for (int i = tid; i < 128 * 16; i += 512) {
        int lr = i >> 4, g = i & 15;
        int r = r0 + lr;
        float4 v = make_float4(0.f, 0.f, 0.f, 0.f);
        if (r < N_ATOMS) v = *(const float4*)(atom + (size_t)r * 64 + g * 4);
        __half2* d = (__half2*)(As + lr * PQ_ALD + g * 4);
        d[0] = __floats2half2_rn(v.x, v.y);
        d[1] = __floats2half2_rn(v.z, v.w);
    }
    __syncthreads();

    const int w  = tid >> 5;
    const int wr = w & 3;
    const int wc = w >> 2;

    wmma::fragment<wmma::accumulator, 16, 16, 16, float> c[2][4];
    #pragma unroll
    for (int i = 0; i < 2; i++)
        #pragma unroll
        for (int j = 0; j < 4; j++) wmma::fill_fragment(c[i][j], 0.f);

    #pragma unroll
    for (int k = 0; k < 64; k += 16) {
        wmma::fragment<wmma::matrix_a, 16, 16, 16, __half, wmma::row_major> a[2];
        wmma::fragment<wmma::matrix_b, 16, 16, 16, __half, wmma::row_major> b[4];
        #pragma unroll
        for (int i = 0; i < 2; i++)
            wmma::load_matrix_sync(a[i], As + (wr * 32 + i * 16) * PQ_ALD + k, PQ_ALD);
        #pragma unroll
        for (int j = 0; j < 4; j++)
            wmma::load_matrix_sync(b[j], Bs + k * PQ_BLD + wc * 64 + j * 16, PQ_BLD);
        #pragma unroll
        for (int i = 0; i < 2; i++)
            #pragma unroll
            for (int j = 0; j < 4; j++)
                wmma::mma_sync(c[i][j], a[i], b[j], c[i][j]);
    }
    __syncthreads();

    #pragma unroll
    for (int h = 0; h < 2; h++) {
        if ((wc >> 1) == h) {
            #pragma unroll
            for (int i = 0; i < 2; i++)
                #pragma unroll
                for (int j = 0; j < 4; j++)
                    wmma::store_matrix_sync(cs + (wr * 32 + i * 16) * CLD + (wc & 1) * 64 + j * 16,
                                            c[i][j], CLD, wmma::mem_row_major);
        }
        __syncthreads();
        for (int i = tid; i < 128 * 64; i += 512) {
            int r = i >> 6, c2 = (i & 63) * 2;
            int R = r0 + r;
            if (R < N_ATOMS) {
                float v0 = cs[r * CLD + c2];
                float v1 = cs[r * CLD + c2 + 1];
                if (h == 0) {
                    v0 += bs[c2]; v1 += bs[c2 + 1];
                    *(__half2*)(g_p + (size_t)R * 128 + c2) = __floats2half2_rn(v0, v1);
                } else {
                    *(__half2*)(g_q + (size_t)R * 128 + c2) = __floats2half2_rn(v0, v1);
                }
            }
        }
        __syncthreads();
    }
}

// ---------------- kernel 2: R = nbr@W3^T ; g = R + P[n] + Q[idx] ; BN1 stats ; fp16 store ----------------
// 64-row x 128-col tile, 256 threads, 8 warps of 32x32 WMMA.
// B fragments loaded directly from global g_w3 (L1-resident, no smem copy).
// cs staged in fp16 (half-accumulator store) -> halves the cs L1 round-trip.
#define M_ALD  56
#define CLDH   136
#define M_SMA  0                          // As 64*56*2 = 7168 (overlaid by csh after mainloop)
#define M_CSH  0                          // csh 64*136*2 = 17408
#define M_IDX  17408                      // 64 ints
#define M_SN   (17408 + 256)              // 64 ints
#define M_PS   (17408 + 512)              // 7*128 halves = 1792
#define M_PSUM (17408 + 512 + 1792)       // 4*128 floats = 2048
#define M_PSQ  (M_PSUM + 2048)
#define M_SM   (M_PSQ + 2048)             // 23808

__global__ void __launch_bounds__(256, 5) main_kernel(const float* __restrict__ nbr,
                                                      const int*   __restrict__ idx,
                                                      int tile0) {
    extern __shared__ char smem[];
    __half* As   = (__half*)(smem + M_SMA);
    __half* csh  = (__half*)(smem + M_CSH);
    int*    sidx = (int*)(smem + M_IDX);
    int*    sn   = (int*)(smem + M_SN);
    __half* Ps   = (__half*)(smem + M_PS);
    float*  psum = (float*)(smem + M_PSUM);
    float*  psq  = (float*)(smem + M_PSQ);

    const int tid = threadIdx.x;
    const int r0  = (tile0 + blockIdx.x) * 64;
    const int na0 = r0 / 12;
    const int natoms = (r0 + 63) / 12 - na0 + 1;   // <= 7

    if (tid < 64) {
        int R = r0 + tid;
        sidx[tid] = __ldg(idx + R);
        sn[tid]   = R / 12 - na0;
    }
    // stage P rows (fp16) for this tile's atoms
    if (tid < natoms * 16) {
        int row = tid >> 4, seg = tid & 15;
        *(uint4*)(Ps + row * 128 + seg * 8) =
            *(const uint4*)(g_p + (size_t)(na0 + row) * 128 + seg * 8);
    }
    // A: 64 rows x 12 groups of 4 (cols 44..47 zero)
    for (int i = tid; i < 64 * 12; i += 256) {
        int lr = i / 12, g = i % 12;
        const float* nb = nbr + (size_t)(r0 + lr) * 41;
        float v0 = 0.f, v1 = 0.f, v2 = 0.f, v3 = 0.f;
        if (g < 10) { v0 = nb[g*4]; v1 = nb[g*4+1]; v2 = nb[g*4+2]; v3 = nb[g*4+3]; }
        else if (g == 10) { v0 = nb[40]; }
        __half2* d = (__half2*)(As + lr * M_ALD + g * 4);
        d[0] = __floats2half2_rn(v0, v1);
        d[1] = __floats2half2_rn(v2, v3);
    }
    __syncthreads();

    // warp -> rows (w&1)*32, cols (w>>1)*32
    const int w  = tid >> 5;
    const int wr = w & 1;
    const int wc = w >> 1;    // 0..3

    wmma::fragment<wmma::accumulator, 16, 16, 16, float> c[2][2];
    #pragma unroll
    for (int i = 0; i < 2; i++)
        #pragma unroll
        for (int j = 0; j < 2; j++) wmma::fill_fragment(c[i][j], 0.f);

    #pragma unroll
    for (int k = 0; k < KP3; k += 16) {
        wmma::fragment<wmma::matrix_a, 16, 16, 16, __half, wmma::row_major> a[2];
        #pragma unroll
        for (int i = 0; i < 2; i++)
            wmma::load_matrix_sync(a[i], As + (wr * 32 + i * 16) * M_ALD + k, M_ALD);
        #pragma unroll
        for (int j = 0; j < 2; j++) {
            wmma::fragment<wmma::matrix_b, 16, 16, 16, __half, wmma::row_major> b;
            wmma::load_matrix_sync(b, g_w3 + k * 128 + wc * 32 + j * 16, 128);  // global, L1-hot
            wmma::mma_sync(c[0][j], a[0], b, c[0][j]);
            wmma::mma_sync(c[1][j], a[1], b, c[1][j]);
        }
    }
    __syncthreads();   // As dead; csh overlays

    // convert f32 accum -> f16 accum fragment, store half tile
    #pragma unroll
    for (int i = 0; i < 2; i++)
        #pragma unroll
        for (int j = 0; j < 2; j++) {
            wmma::fragment<wmma::accumulator, 16, 16, 16, __half> hc;
            #pragma unroll
            for (int e = 0; e < hc.num_elements; e++)
                hc.x[e] = __float2half_rn(c[i][j].x[e]);
            wmma::store_matrix_sync(csh + (wr * 32 + i * 16) * CLDH + wc * 32 + j * 16,
                                    hc, CLDH, wmma::mem_row_major);
        }
    __syncthreads();

    // epilogue: thread -> channels (cc, cc+1), rows r = rr*4 + rgrp (16 iters)
    // R from csh (half), P from smem, Q gathered as half2 (1-ahead prefetch)
    const int cc   = (tid & 63) * 2;
    const int rgrp = tid >> 6;
    float s0 = 0.f, s1 = 0.f, q0s = 0.f, q1s = 0.f;

    __half2 qh_cur = __ldg((const __half2*)(g_q + (size_t)sidx[rgrp] * 128 + cc));
    #pragma unroll 8
    for (int rr = 0; rr < 16; rr++) {
        int r = rr * 4 + rgrp;
        int R = r0 + r;
        __half2 qh_nxt;
        if (rr < 15)
            qh_nxt = __ldg((const __half2*)(g_q + (size_t)sidx[r + 4] * 128 + cc));
        float2 rv = __half22float2(*(const __half2*)(csh + r * CLDH + cc));
        float2 p  = __half22float2(*(const __half2*)(Ps + sn[r] * 128 + cc));
        float2 q  = __half22float2(qh_cur);
        float g0 = rv.x + p.x + q.x;
        float g1 = rv.y + p.y + q.y;
        ((__half2*)g_gated)[(size_t)R * 64 + (cc >> 1)] = __floats2half2_rn(g0, g1);
        s0 += g0; s1 += g1; q0s += g0 * g0; q1s += g1 * g1;
        qh_cur = qh_nxt;
    }
    __syncthreads();
    psum[rgrp * 128 + cc] = s0;  psum[rgrp * 128 + cc + 1] = s1;
    psq [rgrp * 128 + cc] = q0s; psq [rgrp * 128 + cc + 1] = q1s;
    __syncthreads();
    if (tid < 128) {
        float s = psum[tid] + psum[128 + tid] + psum[256 + tid] + psum[384 + tid];
        float q = psq[tid]  + psq[128 + tid]  + psq[256 + tid]  + psq[384 + tid];
        int st = (tile0 + blockIdx.x) & (NSTRIPE - 1);
        atomicAdd(&g_stats1[st][tid],       (double)s);
        atomicAdd(&g_stats1[st][128 + tid], (double)q);
    }
}

// ---------------- kernel 3: finalize BN1 (512 thr = 128 ch x 4 stripe-groups) ----------------
__global__ void bn1_fin(const float* __restrict__ gamma, const float* __restrict__ beta) {
    __shared__ double rs[4][128], rq[4][128];
    int c  = threadIdx.x & 127;
    int sg = threadIdx.x >> 7;
    double s = 0.0, s2 = 0.0;
    #pragma unroll
    for (int k = 0; k < 16; k++) {
        int st = sg * 16 + k;
        s  += g_stats1[st][c];
        s2 += g_stats1[st][128 + c];
    }
    rs[sg][c] = s; rq[sg][c] = s2;
    __syncthreads();
    if (threadIdx.x < 128) {
        double S  = rs[0][c] + rs[1][c] + rs[2][c] + rs[3][c];
        double S2 = rq[0][c] + rq[1][c] + rq[2][c] + rq[3][c];
        double mean = S / (double)NROWS;
        double var  = S2 / (double)NROWS - mean * mean;
        float sc = gamma[c] * rsqrtf((float)var + BN_EPS);
        g_bn1_scale[c] = sc;
        g_bn1_shift[c] = beta[c] - (float)mean * sc;
    }
}

// ---------------- kernel 4: gate ----------------
__global__ void gate_kernel() {
    const int lane = threadIdx.x & 31;
    const int w    = threadIdx.x >> 5;
    const int n    = blockIdx.x * 8 + w;

    __shared__ float ssum[64], ssq[64];
    if (threadIdx.x < 64) { ssum[threadIdx.x] = 0.f; ssq[threadIdx.x] = 0.f; }
    __syncthreads();

    const float2 sc1 = *(const float2*)(g_bn1_scale + 2 * lane);
    const float2 sh1 = *(const float2*)(g_bn1_shift + 2 * lane);
    const float2 sc2 = *(const float2*)(g_bn1_scale + 64 + 2 * lane);
    const float2 sh2 = *(const float2*)(g_bn1_shift + 64 + 2 * lane);

    float2 acc = make_float2(0.f, 0.f);
    const __half2* gp = (const __half2*)(g_gated + (size_t)n * 12 * OUT_DIM);
    #pragma unroll
    for (int m = 0; m < 12; m++) {
        float2 a = __half22float2(gp[m * 64 + lane]);
        float2 b = __half22float2(gp[m * 64 + 32 + lane]);
        a.x = a.x * sc1.x + sh1.x;  a.y = a.y * sc1.y + sh1.y;
        b.x = b.x * sc2.x + sh2.x;  b.y = b.y * sc2.y + sh2.y;
        acc.x += sigmoid_f(a.x) * softplus_f(b.x);
        acc.y += sigmoid_f(a.y) * softplus_f(b.y);
    }
    ((float2*)(g_nbrsum + (size_t)n * 64))[lane] = acc;

    atomicAdd(&ssum[2 * lane],     acc.x);
    atomicAdd(&ssum[2 * lane + 1], acc.y);
    atomicAdd(&ssq[2 * lane],      acc.x * acc.x);
    atomicAdd(&ssq[2 * lane + 1],  acc.y * acc.y);
    __syncthreads();
    if (threadIdx.x < 64) {
        int st = blockIdx.x & (NSTRIPE - 1);
        atomicAdd(&g_stats2[st][threadIdx.x],      (double)ssum[threadIdx.x]);
        atomicAdd(&g_stats2[st][64 + threadIdx.x], (double)ssq[threadIdx.x]);
    }
}

// ---------------- kernel 5: finalize BN2 (256 thr = 64 ch x 4 groups) ----------------
__global__ void bn2_fin(const float* __restrict__ gamma, const float* __restrict__ beta) {
    __shared__ double rs[4][64], rq[4][64];
    int c  = threadIdx.x & 63;
    int sg = threadIdx.x >> 6;
    double s = 0.0, s2 = 0.0;
    #pragma unroll
    for (int k = 0; k < 16; k++) {
        int st = sg * 16 + k;
        s  += g_stats2[st][c];
        s2 += g_stats2[st][64 + c];
    }
    rs[sg][c] = s; rq[sg][c] = s2;
    __syncthreads();
    if (threadIdx.x < 64) {
        double S  = rs[0][c] + rs[1][c] + rs[2][c] + rs[3][c];
        double S2 = rq[0][c] + rq[1][c] + rq[2][c] + rq[3][c];
        double mean = S / (double)N_ATOMS;
        double var  = S2 / (double)N_ATOMS - mean * mean;
        float sc = gamma[c] * rsqrtf((float)var + BN_EPS);
        g_bn2_scale[c] = sc;
        g_bn2_shift[c] = beta[c] - (float)mean * sc;
    }
}

// ---------------- kernel 6: residual + softplus ----------------
__global__ void final_kernel(const float* __restrict__ atom, float* __restrict__ out) {
    int i = blockIdx.x * 256 + threadIdx.x;
    if (i >= N_ATOMS * F_ATOM) return;
    int o = i & 63;
    float v = atom[i] + g_nbrsum[i] * g_bn2_scale[o] + g_bn2_shift[o];
    out[i] = softplus_f(v);
}

// ---------------- launch ----------------
extern "C" void kernel_launch(void* const* d_in, const int* in_sizes, int n_in,
                              void* d_out, int out_size) {
    const float* atom = (const float*)d_in[0];
    const float* nbr  = (const float*)d_in[1];
    const int*   idx  = (const int*)  d_in[2];
    const float* fcw  = (const float*)d_in[3];
    const float* fcb  = (const float*)d_in[4];
    const float* g1   = (const float*)d_in[5];
    const float* b1   = (const float*)d_in[6];
    const float* g2   = (const float*)d_in[7];
    const float* b2   = (const float*)d_in[8];
    float* out = (float*)d_out;

    cudaFuncSetAttribute(pq_kernel,   cudaFuncAttributeMaxDynamicSharedMemorySize, PQ_SM);
    cudaFuncSetAttribute(main_kernel, cudaFuncAttributeMaxDynamicSharedMemorySize, M_SM);

    prep_kernel<<<64, 256>>>(fcw);
    pq_kernel<<<PQTILES, 512, PQ_SM>>>(atom, fcb);
    // split so the ncu capture (4th launch) profiles main_kernel chunk 2
    main_kernel<<<MTILES / 2, 256, M_SM>>>(nbr, idx, 0);
    main_kernel<<<MTILES / 2, 256, M_SM>>>(nbr, idx, MTILES / 2);
    bn1_fin<<<1, 512>>>(g1, b1);
    gate_kernel<<<N_ATOMS / 8, 256>>>();
    bn2_fin<<<1, 256>>>(g2, b2);
    final_kernel<<<(N_ATOMS * F_ATOM + 255) / 256, 256>>>(atom, out);
}

// round 17
// speedup vs baseline: 1.1720x; 1.1720x over previous
#include <cuda_runtime.h>
#include <cuda_fp16.h>
#include <mma.h>
#include <cstdint>

using namespace nvcuda;

// ---------------- problem constants ----------------
#define N_ATOMS 100000
#define M_NBR   12
#define F_ATOM  64
#define IN_DIM  169
#define OUT_DIM 128
#define NROWS   (N_ATOMS * M_NBR)        // 1,200,000
#define MTILES  (NROWS / 64)             // 18750 (64-row tiles)
#define PQTILES ((N_ATOMS + 127) / 128)  // 782
#define KP3     48
#define NSTRIPE 64
#define BN_EPS  1e-5f

// ---------------- device scratch ----------------
__device__ __align__(16) __half g_w12[64 * 256];      // [k][o]: o<128 -> W1, o>=128 -> W2
__device__ __align__(16) __half g_w3[KP3 * 128];      // [k][o], rows 41..47 zero
__device__ __align__(16) __half g_p[(size_t)N_ATOMS * 128];   // P + bias, fp16
__device__ __align__(16) __half g_q[(size_t)N_ATOMS * 128];   // Q, fp16
__device__ __half  g_gated[(size_t)NROWS * OUT_DIM];  // 307 MB
__device__ float   g_nbrsum[N_ATOMS * F_ATOM];
__device__ double  g_stats1[NSTRIPE][2 * OUT_DIM];
__device__ double  g_stats2[NSTRIPE][2 * F_ATOM];
__device__ float   g_bn1_scale[OUT_DIM], g_bn1_shift[OUT_DIM];
__device__ float   g_bn2_scale[F_ATOM],  g_bn2_shift[F_ATOM];

// ---------------- fast activations ----------------
__device__ __forceinline__ float softplus_f(float x) {
    return fmaxf(x, 0.f) + __logf(1.f + __expf(-fabsf(x)));
}
__device__ __forceinline__ float sigmoid_f(float x) {
    return __fdividef(1.f, 1.f + __expf(-x));
}

// ---------------- kernel 0: zero stats + build fp16 weight images ----------------
__global__ void prep_kernel(const float* __restrict__ fc_w) {
    int i = blockIdx.x * 256 + threadIdx.x;   // 64*256 = 16384
    if (i < NSTRIPE * 2 * OUT_DIM) ((double*)g_stats1)[i] = 0.0;
    if (i < NSTRIPE * 2 * F_ATOM)  ((double*)g_stats2)[i] = 0.0;
    if (i < 64 * 256) {
        int k = i >> 8, c = i & 255;
        float v = (c < 128) ? fc_w[c * IN_DIM + k] : fc_w[(c - 128) * IN_DIM + 64 + k];
        g_w12[i] = __float2half_rn(v);
    }
    if (i < KP3 * 128) {
        int k = i >> 7, o = i & 127;
        g_w3[i] = __float2half_rn(k < 41 ? fc_w[o * IN_DIM + 128 + k] : 0.f);
    }
}

// ---------------- kernel 1: P = atom@W1^T + b (fp16), Q = atom@W2^T (fp16) ----------------
#define PQ_ALD  72
#define PQ_BLD  264
#define PQ_SMA  0
#define PQ_SMB  18432
#define PQ_CS   0
#define PQ_BIAS 67584
#define PQ_SM   (67584 + 512)
#define CLD     132

__global__ void __launch_bounds__(512, 1) pq_kernel(const float* __restrict__ atom,
                                                    const float* __restrict__ bias) {
    extern __shared__ char smem[];
    __half* As = (__half*)(smem + PQ_SMA);
    __half* Bs = (__half*)(smem + PQ_SMB);
    float*  cs = (float*)(smem + PQ_CS);
    float*  bs = (float*)(smem + PQ_BIAS);

    const int tid = threadIdx.x;
    const int r0  = blockIdx.x * 128;

    if (tid < 128) bs[tid] = bias[tid];

    for (int i = tid; i < 64 * 32; i += 512) {
        int row = i >> 5, seg = i & 31;
        *(uint4*)(Bs + row * PQ_BLD + seg * 8) = *(const uint4*)(g_w12 + row * 256 + seg * 8);
    }
    for (int i = tid; i < 128 * 16; i += 512) {
        int lr = i >> 4, g = i & 15;
        int r = r0 + lr;
        float4 v = make_float4(0.f, 0.f, 0.f, 0.f);
        if (r < N_ATOMS) v = *(const float4*)(atom + (size_t)r * 64 + g * 4);
        __half2* d = (__half2*)(As + lr * PQ_ALD + g * 4);
        d[0] = __floats2half2_rn(v.x, v.y);
        d[1] = __floats2half2_rn(v.z, v.w);
    }
    __syncthreads();

    const int w  = tid >> 5;
    const int wr = w & 3;
    const int wc = w >> 2;

    wmma::fragment<wmma::accumulator, 16, 16, 16, float> c[2][4];
    #pragma unroll
    for (int i = 0; i < 2; i++)
        #pragma unroll
        for (int j = 0; j < 4; j++) wmma::fill_fragment(c[i][j], 0.f);

    #pragma unroll
    for (int k = 0; k < 64; k += 16) {
        wmma::fragment<wmma::matrix_a, 16, 16, 16, __half, wmma::row_major> a[2];
        wmma::fragment<wmma::matrix_b, 16, 16, 16, __half, wmma::row_major> b[4];
        #pragma unroll
        for (int i = 0; i < 2; i++)
            wmma::load_matrix_sync(a[i], As + (wr * 32 + i * 16) * PQ_ALD + k, PQ_ALD);
        #pragma unroll
        for (int j = 0; j < 4; j++)
            wmma::load_matrix_sync(b[j], Bs + k * PQ_BLD + wc * 64 + j * 16, PQ_BLD);
        #pragma unroll
        for (int i = 0; i < 2; i++)
            #pragma unroll
            for (int j = 0; j < 4; j++)
                wmma::mma_sync(c[i][j], a[i], b[j], c[i][j]);
    }
    __syncthreads();

    #pragma unroll
    for (int h = 0; h < 2; h++) {
        if ((wc >> 1) == h) {
            #pragma unroll
            for (int i = 0; i < 2; i++)
                #pragma unroll
                for (int j = 0; j < 4; j++)
                    wmma::store_matrix_sync(cs + (wr * 32 + i * 16) * CLD + (wc & 1) * 64 + j * 16,
                                            c[i][j], CLD, wmma::mem_row_major);
        }
        __syncthreads();
        for (int i = tid; i < 128 * 64; i += 512) {
            int r = i >> 6, c2 = (i & 63) * 2;
            int R = r0 + r;
            if (R < N_ATOMS) {
                float v0 = cs[r * CLD + c2];
                float v1 = cs[r * CLD + c2 + 1];
                if (h == 0) {
                    v0 += bs[c2]; v1 += bs[c2 + 1];
                    *(__half2*)(g_p + (size_t)R * 128 + c2) = __floats2half2_rn(v0, v1);
                } else {
                    *(__half2*)(g_q + (size_t)R * 128 + c2) = __floats2half2_rn(v0, v1);
                }
            }
        }
        __syncthreads();
    }
}

// ---------------- kernel 2: R = nbr@W3^T ; g = R + P[n] + Q[idx] ; BN1 stats ; fp16 store ----------------
// 64-row x 128-col tile, 256 threads, 8 warps of 32x32 WMMA (R14 structure).
// B in smem (vectorized copy, broadcast LDS). cs staged in fp16 (halved round-trip).
#define M_ALD  56
#define M_BLD  136
#define CLDH   136
#define M_SMA  0                          // As 64*56*2 = 7168
#define M_SMB  7168                       // Bs 48*136*2 = 13056 -> ends 20224
#define M_CSH  0                          // csh 64*136*2 = 17408 (overlays As+Bs head)
#define M_IDX  20224                      // 64 ints
#define M_SN   (20224 + 256)              // 64 ints
#define M_PS   (20224 + 512)              // 7*128 halves = 1792 -> 22528
#define M_PSUM 22528                      // 4*128 floats = 2048
#define M_PSQ  (22528 + 2048)             // 2048
#define M_SM   (M_PSQ + 2048)             // 26624

__global__ void __launch_bounds__(256, 5) main_kernel(const float* __restrict__ nbr,
                                                      const int*   __restrict__ idx,
                                                      int tile0) {
    extern __shared__ char smem[];
    __half* As   = (__half*)(smem + M_SMA);
    __half* Bs   = (__half*)(smem + M_SMB);
    __half* csh  = (__half*)(smem + M_CSH);
    int*    sidx = (int*)(smem + M_IDX);
    int*    sn   = (int*)(smem + M_SN);
    __half* Ps   = (__half*)(smem + M_PS);
    float*  psum = (float*)(smem + M_PSUM);
    float*  psq  = (float*)(smem + M_PSQ);

    const int tid = threadIdx.x;
    const int r0  = (tile0 + blockIdx.x) * 64;
    const int na0 = r0 / 12;
    const int natoms = (r0 + 63) / 12 - na0 + 1;   // <= 7

    if (tid < 64) {
        int R = r0 + tid;
        sidx[tid] = __ldg(idx + R);
        sn[tid]   = R / 12 - na0;
    }
    // stage P rows (fp16) for this tile's atoms
    if (tid < natoms * 16) {
        int row = tid >> 4, seg = tid & 15;
        *(uint4*)(Ps + row * 128 + seg * 8) =
            *(const uint4*)(g_p + (size_t)(na0 + row) * 128 + seg * 8);
    }
    // B: 48 rows x 128 halves, stride 136 (vectorized copy)
    for (int i = tid; i < KP3 * 16; i += 256) {
        int row = i >> 4, seg = i & 15;
        *(uint4*)(Bs + row * M_BLD + seg * 8) = *(const uint4*)(g_w3 + row * 128 + seg * 8);
    }
    // A: 64 rows x 12 groups of 4 (cols 44..47 zero)
    for (int i = tid; i < 64 * 12; i += 256) {
        int lr = i / 12, g = i % 12;
        const float* nb = nbr + (size_t)(r0 + lr) * 41;
        float v0 = 0.f, v1 = 0.f, v2 = 0.f, v3 = 0.f;
        if (g < 10) { v0 = nb[g*4]; v1 = nb[g*4+1]; v2 = nb[g*4+2]; v3 = nb[g*4+3]; }
        else if (g == 10) { v0 = nb[40]; }
        __half2* d = (__half2*)(As + lr * M_ALD + g * 4);
        d[0] = __floats2half2_rn(v0, v1);
        d[1] = __floats2half2_rn(v2, v3);
    }
    __syncthreads();

    // warp -> rows (w&1)*32, cols (w>>1)*32
    const int w  = tid >> 5;
    const int wr = w & 1;
    const int wc = w >> 1;    // 0..3

    wmma::fragment<wmma::accumulator, 16, 16, 16, float> c[2][2];
    #pragma unroll
    for (int i = 0; i < 2; i++)
        #pragma unroll
        for (int j = 0; j < 2; j++) wmma::fill_fragment(c[i][j], 0.f);

    #pragma unroll
    for (int k = 0; k < KP3; k += 16) {
        wmma::fragment<wmma::matrix_a, 16, 16, 16, __half, wmma::row_major> a[2];
        #pragma unroll
        for (int i = 0; i < 2; i++)
            wmma::load_matrix_sync(a[i], As + (wr * 32 + i * 16) * M_ALD + k, M_ALD);
        #pragma unroll
        for (int j = 0; j < 2; j++) {
            wmma::fragment<wmma::matrix_b, 16, 16, 16, __half, wmma::row_major> b;
            wmma::load_matrix_sync(b, Bs + k * M_BLD + wc * 32 + j * 16, M_BLD);
            wmma::mma_sync(c[0][j], a[0], b, c[0][j]);
            wmma::mma_sync(c[1][j], a[1], b, c[1][j]);
        }
    }
    __syncthreads();   // As/Bs dead; csh overlays

    // convert f32 accum -> f16 accum fragment, store half tile
    #pragma unroll
    for (int i = 0; i < 2; i++)
        #pragma unroll
        for (int j = 0; j < 2; j++) {
            wmma::fragment<wmma::accumulator, 16, 16, 16, __half> hc;
            #pragma unroll
            for (int e = 0; e < hc.num_elements; e++)
                hc.x[e] = __float2half_rn(c[i][j].x[e]);
            wmma::store_matrix_sync(csh + (wr * 32 + i * 16) * CLDH + wc * 32 + j * 16,
                                    hc, CLDH, wmma::mem_row_major);
        }
    __syncthreads();

    // epilogue: thread -> channels (cc, cc+1), rows r = rr*4 + rgrp (16 iters)
    const int cc   = (tid & 63) * 2;
    const int rgrp = tid >> 6;
    float s0 = 0.f, s1 = 0.f, q0s = 0.f, q1s = 0.f;

    __half2 qh_cur = __ldg((const __half2*)(g_q + (size_t)sidx[rgrp] * 128 + cc));
    #pragma unroll 8
    for (int rr = 0; rr < 16; rr++) {
        int r = rr * 4 + rgrp;
        int R = r0 + r;
        __half2 qh_nxt;
        if (rr < 15)
            qh_nxt = __ldg((const __half2*)(g_q + (size_t)sidx[r + 4] * 128 + cc));
        float2 rv = __half22float2(*(const __half2*)(csh + r * CLDH + cc));
        float2 p  = __half22float2(*(const __half2*)(Ps + sn[r] * 128 + cc));
        float2 q  = __half22float2(qh_cur);
        float g0 = rv.x + p.x + q.x;
        float g1 = rv.y + p.y + q.y;
        ((__half2*)g_gated)[(size_t)R * 64 + (cc >> 1)] = __floats2half2_rn(g0, g1);
        s0 += g0; s1 += g1; q0s += g0 * g0; q1s += g1 * g1;
        qh_cur = qh_nxt;
    }
    __syncthreads();
    psum[rgrp * 128 + cc] = s0;  psum[rgrp * 128 + cc + 1] = s1;
    psq [rgrp * 128 + cc] = q0s; psq [rgrp * 128 + cc + 1] = q1s;
    __syncthreads();
    if (tid < 128) {
        float s = psum[tid] + psum[128 + tid] + psum[256 + tid] + psum[384 + tid];
        float q = psq[tid]  + psq[128 + tid]  + psq[256 + tid]  + psq[384 + tid];
        int st = (tile0 + blockIdx.x) & (NSTRIPE - 1);
        atomicAdd(&g_stats1[st][tid],       (double)s);
        atomicAdd(&g_stats1[st][128 + tid], (double)q);
    }
}

// ---------------- kernel 3: finalize BN1 (512 thr = 128 ch x 4 stripe-groups) ----------------
__global__ void bn1_fin(const float* __restrict__ gamma, const float* __restrict__ beta) {
    __shared__ double rs[4][128], rq[4][128];
    int c  = threadIdx.x & 127;
    int sg = threadIdx.x >> 7;
    double s = 0.0, s2 = 0.0;
    #pragma unroll
    for (int k = 0; k < 16; k++) {
        int st = sg * 16 + k;
        s  += g_stats1[st][c];
        s2 += g_stats1[st][128 + c];
    }
    rs[sg][c] = s; rq[sg][c] = s2;
    __syncthreads();
    if (threadIdx.x < 128) {
        double S  = rs[0][c] + rs[1][c] + rs[2][c] + rs[3][c];
        double S2 = rq[0][c] + rq[1][c] + rq[2][c] + rq[3][c];
        double mean = S / (double)NROWS;
        double var  = S2 / (double)NROWS - mean * mean;
        float sc = gamma[c] * rsqrtf((float)var + BN_EPS);
        g_bn1_scale[c] = sc;
        g_bn1_shift[c] = beta[c] - (float)mean * sc;
    }
}

// ---------------- kernel 4: gate ----------------
__global__ void gate_kernel() {
    const int lane = threadIdx.x & 31;
    const int w    = threadIdx.x >> 5;
    const int n    = blockIdx.x * 8 + w;

    __shared__ float ssum[64], ssq[64];
    if (threadIdx.x < 64) { ssum[threadIdx.x] = 0.f; ssq[threadIdx.x] = 0.f; }
    __syncthreads();

    const float2 sc1 = *(const float2*)(g_bn1_scale + 2 * lane);
    const float2 sh1 = *(const float2*)(g_bn1_shift + 2 * lane);
    const float2 sc2 = *(const float2*)(g_bn1_scale + 64 + 2 * lane);
    const float2 sh2 = *(const float2*)(g_bn1_shift + 64 + 2 * lane);

    float2 acc = make_float2(0.f, 0.f);
    const __half2* gp = (const __half2*)(g_gated + (size_t)n * 12 * OUT_DIM);
    #pragma unroll
    for (int m = 0; m < 12; m++) {
        float2 a = __half22float2(gp[m * 64 + lane]);
        float2 b = __half22float2(gp[m * 64 + 32 + lane]);
        a.x = a.x * sc1.x + sh1.x;  a.y = a.y * sc1.y + sh1.y;
        b.x = b.x * sc2.x + sh2.x;  b.y = b.y * sc2.y + sh2.y;
        acc.x += sigmoid_f(a.x) * softplus_f(b.x);
        acc.y += sigmoid_f(a.y) * softplus_f(b.y);
    }
    ((float2*)(g_nbrsum + (size_t)n * 64))[lane] = acc;

    atomicAdd(&ssum[2 * lane],     acc.x);
    atomicAdd(&ssum[2 * lane + 1], acc.y);
    atomicAdd(&ssq[2 * lane],      acc.x * acc.x);
    atomicAdd(&ssq[2 * lane + 1],  acc.y * acc.y);
    __syncthreads();
    if (threadIdx.x < 64) {
        int st = blockIdx.x & (NSTRIPE - 1);
        atomicAdd(&g_stats2[st][threadIdx.x],      (double)ssum[threadIdx.x]);
        atomicAdd(&g_stats2[st][64 + threadIdx.x], (double)ssq[threadIdx.x]);
    }
}

// ---------------- kernel 5: finalize BN2 (256 thr = 64 ch x 4 groups) ----------------
__global__ void bn2_fin(const float* __restrict__ gamma, const float* __restrict__ beta) {
    __shared__ double rs[4][64], rq[4][64];
    int c  = threadIdx.x & 63;
    int sg = threadIdx.x >> 6;
    double s = 0.0, s2 = 0.0;
    #pragma unroll
    for (int k = 0; k < 16; k++) {
        int st = sg * 16 + k;
        s  += g_stats2[st][c];
        s2 += g_stats2[st][64 + c];
    }
    rs[sg][c] = s; rq[sg][c] = s2;
    __syncthreads();
    if (threadIdx.x < 64) {
        double S  = rs[0][c] + rs[1][c] + rs[2][c] + rs[3][c];
        double S2 = rq[0][c] + rq[1][c] + rq[2][c] + rq[3][c];
        double mean = S / (double)N_ATOMS;
        double var  = S2 / (double)N_ATOMS - mean * mean;
        float sc = gamma[c] * rsqrtf((float)var + BN_EPS);
        g_bn2_scale[c] = sc;
        g_bn2_shift[c] = beta[c] - (float)mean * sc;
    }
}

// ---------------- kernel 6: residual + softplus ----------------
__global__ void final_kernel(const float* __restrict__ atom, float* __restrict__ out) {
    int i = blockIdx.x * 256 + threadIdx.x;
    if (i >= N_ATOMS * F_ATOM) return;
    int o = i & 63;
    float v = atom[i] + g_nbrsum[i] * g_bn2_scale[o] + g_bn2_shift[o];
    out[i] = softplus_f(v);
}

// ---------------- launch ----------------
extern "C" void kernel_launch(void* const* d_in, const int* in_sizes, int n_in,
                              void* d_out, int out_size) {
    const float* atom = (const float*)d_in[0];
    const float* nbr  = (const float*)d_in[1];
    const int*   idx  = (const int*)  d_in[2];
    const float* fcw  = (const float*)d_in[3];
    const float* fcb  = (const float*)d_in[4];
    const float* g1   = (const float*)d_in[5];
    const float* b1   = (const float*)d_in[6];
    const float* g2   = (const float*)d_in[7];
    const float* b2   = (const float*)d_in[8];
    float* out = (float*)d_out;

    cudaFuncSetAttribute(pq_kernel,   cudaFuncAttributeMaxDynamicSharedMemorySize, PQ_SM);
    cudaFuncSetAttribute(main_kernel, cudaFuncAttributeMaxDynamicSharedMemorySize, M_SM);

    prep_kernel<<<64, 256>>>(fcw);
    pq_kernel<<<PQTILES, 512, PQ_SM>>>(atom, fcb);
    // split so the ncu capture (4th launch) profiles main_kernel chunk 2
    main_kernel<<<MTILES / 2, 256, M_SM>>>(nbr, idx, 0);
    main_kernel<<<MTILES / 2, 256, M_SM>>>(nbr, idx, MTILES / 2);
    bn1_fin<<<1, 512>>>(g1, b1);
    gate_kernel<<<N_ATOMS / 8, 256>>>();
    bn2_fin<<<1, 256>>>(g2, b2);
    final_kernel<<<(N_ATOMS * F_ATOM + 255) / 256, 256>>>(atom, out);
}